// round 11
// baseline (speedup 1.0000x reference)
#include <cuda_runtime.h>
#include <math.h>

#define BB 4
#define HH 64
#define WW 64
#define CC 128
#define PP 4096
#define SPLITS 9
#define GX 16
#define ROWS_PB 256
#define LOG2E 1.44269504088896340736f

typedef unsigned long long ull;

// ---------------- static scratch ----------------
__device__ float g_x[BB * PP * 2];          // per-pixel (mean, max)
__device__ float g_xfq[BB * PP * 20];       // queries pre-scaled by LOG2E, 18+2 pad
__device__ float g_M[BB * PP];              // M2 = patch L2 norm * LOG2E
__device__ float g_wn[BB * PP * 20];        // compacted normalized keys, 18+2 pad
__device__ float g_xfe[BB * PP * 12];       // compacted taps [t0..t8, 1.0, 0, 0]
__device__ float g_sig[BB * PP];            // sigmoid(gate conv)
__device__ int   g_vrank[PP];               // pixel -> compacted key index (or -1)
__device__ int   g_need[PP];
__device__ int   g_counts[2];               // [0]=n_valid, [1]=n_need
__device__ ull   g_pa[(size_t)BB * SPLITS * PP * 5];  // packed split partials (9 taps + l)
__device__ float g_tmp9[BB * PP * 9];
__device__ int   g_cnt[BB * GX];            // split arrival counters (self-resetting)

// ---- packed f32x2 helpers ----
__device__ __forceinline__ ull pk2(float lo, float hi) {
    ull r; asm("mov.b64 %0, {%1, %2};" : "=l"(r) : "f"(lo), "f"(hi)); return r;
}
__device__ __forceinline__ void upk(ull v, float& lo, float& hi) {
    asm("mov.b64 {%0, %1}, %2;" : "=f"(lo), "=f"(hi) : "l"(v));
}
__device__ __forceinline__ ull f2fma(ull a, ull b, ull c) {
    ull d; asm("fma.rn.f32x2 %0, %1, %2, %3;" : "=l"(d) : "l"(a), "l"(b), "l"(c)); return d;
}
__device__ __forceinline__ ull f2mul(ull a, ull b) {
    ull d; asm("mul.rn.f32x2 %0, %1, %2;" : "=l"(d) : "l"(a), "l"(b)); return d;
}
__device__ __forceinline__ ull f2add(ull a, ull b) {
    ull d; asm("add.rn.f32x2 %0, %1, %2;" : "=l"(d) : "l"(a), "l"(b)); return d;
}
__device__ __forceinline__ float ex2f(float x) {
    float r; asm("ex2.approx.f32 %0, %1;" : "=f"(r) : "f"(x)); return r;
}

// ---------------- KA: mean/max (blocks 0..1023, 2 pixels/warp) + compaction (block 1024) ----------------
__global__ void kA(const float* __restrict__ inp, const float* __restrict__ mask) {
    __shared__ int wv[8], wn_[8];
    if (blockIdx.x == 1024) {
        int t = threadIdx.x;
        int lane = t & 31, wid = t >> 5;
        unsigned fv = 0, fn = 0;
        int cv = 0, cn = 0;
        int base_p = t * 16;
        for (int i = 0; i < 16; i++) {
            int p = base_p + i, y = p >> 6, x = p & 63;
            int allone = 1, anyz = 0;
            #pragma unroll
            for (int dy = -1; dy <= 1; dy++)
                #pragma unroll
                for (int dx = -1; dx <= 1; dx++) {
                    int yy = y + dy, xx = x + dx;
                    if (yy < 0 || yy >= HH || xx < 0 || xx >= WW) {
                        allone = 0;
                    } else {
                        float mv = mask[(yy << 6) + xx];
                        if (mv < 0.5f) { allone = 0; anyz = 1; }
                    }
                }
            if (allone) { fv |= (1u << i); cv++; }
            if (anyz)   { fn |= (1u << i); cn++; }
        }
        int iv = cv, inn = cn;
        #pragma unroll
        for (int o = 1; o < 32; o <<= 1) {
            int a = __shfl_up_sync(0xffffffffu, iv, o);
            int b = __shfl_up_sync(0xffffffffu, inn, o);
            if (lane >= o) { iv += a; inn += b; }
        }
        if (lane == 31) { wv[wid] = iv; wn_[wid] = inn; }
        __syncthreads();
        int bv = 0, bn = 0;
        for (int i = 0; i < wid; i++) { bv += wv[i]; bn += wn_[i]; }
        int offv = bv + iv - cv;
        int offn = bn + inn - cn;
        for (int i = 0; i < 16; i++) {
            int p = base_p + i;
            if (fv & (1u << i)) g_vrank[p] = offv++;
            else                g_vrank[p] = -1;
            if (fn & (1u << i)) g_need[offn++] = p;
        }
        if (t == 255) { g_counts[0] = bv + iv; g_counts[1] = bn + inn; }
        return;
    }
    // 2 pixels per warp: 16-lane group each
    int lane = threadIdx.x & 31;
    int pix = blockIdx.x * 16 + (threadIdx.x >> 5) * 2 + (lane >> 4);
    int sub = lane & 15;
    const float4* base = (const float4*)(inp + (size_t)pix * CC);
    float4 v1 = base[sub];
    float4 v2 = base[sub + 16];
    float s = ((v1.x + v1.y) + (v1.z + v1.w)) + ((v2.x + v2.y) + (v2.z + v2.w));
    float m = fmaxf(fmaxf(fmaxf(v1.x, v1.y), fmaxf(v1.z, v1.w)),
                    fmaxf(fmaxf(v2.x, v2.y), fmaxf(v2.z, v2.w)));
    #pragma unroll
    for (int o = 8; o; o >>= 1) {
        s += __shfl_xor_sync(0xffffffffu, s, o);
        m = fmaxf(m, __shfl_xor_sync(0xffffffffu, m, o));
    }
    if (sub == 0) {
        g_x[pix * 2 + 0] = s * (1.0f / 128.0f);
        g_x[pix * 2 + 1] = m;
    }
}

// ---------------- KB: patch vectors + norms + compacted keys/values + gate conv ----------------
__global__ void kB_patches(const float* __restrict__ convw) {
    int idx = blockIdx.x * blockDim.x + threadIdx.x;   // BB*PP
    if (idx >= BB * PP) return;
    int p = idx & 4095, y = p >> 6, x = p & 63;
    int b = idx >> 12;
    float v[18];
    float ss = 0.f;
    int j = 0;
    #pragma unroll
    for (int kh = 0; kh < 3; kh++)
        #pragma unroll
        for (int kw = 0; kw < 3; kw++) {
            int yy = y + kh - 1, xx = x + kw - 1;
            float a = 0.f, c1 = 0.f;
            if (yy >= 0 && yy < HH && xx >= 0 && xx < WW) {
                int q = (b << 12) + (yy << 6) + xx;
                a  = g_x[q * 2 + 0];
                c1 = g_x[q * 2 + 1];
            }
            v[j] = a; v[j + 1] = c1;
            ss += a * a + c1 * c1;
            j += 2;
        }
    float Mn = sqrtf(ss);
    // query: pre-scaled by LOG2E
    float* dst = g_xfq + (size_t)idx * 20;
    #pragma unroll
    for (int i = 0; i < 18; i++) dst[i] = v[i] * LOG2E;
    dst[18] = 0.f; dst[19] = 0.f;
    g_M[idx] = Mn * LOG2E;
    // key/value if this pixel is a fully-valid patch
    int vr = g_vrank[p];
    if (vr >= 0) {
        float rn = 1.f / fmaxf(Mn, 1e-4f);
        float* dw = g_wn + (size_t)((b << 12) + vr) * 20;
        #pragma unroll
        for (int i = 0; i < 18; i++) dw[i] = v[i] * rn;
        dw[18] = 0.f; dw[19] = 0.f;
        float* de = g_xfe + (size_t)((b << 12) + vr) * 12;
        #pragma unroll
        for (int k = 0; k < 9; k++) de[k] = v[2 * k];
        de[9] = 1.0f;          // synthetic tap: accumulates the softmax denominator
        de[10] = 0.f; de[11] = 0.f;
    }
    // 7x7x2 gate conv + sigmoid (independent of attention)
    float g = 0.f;
    #pragma unroll
    for (int u = 0; u < 7; u++) {
        int yy = y + u - 3;
        if (yy < 0 || yy >= HH) continue;
        #pragma unroll
        for (int vv = 0; vv < 7; vv++) {
            int xx = x + vv - 3;
            if (xx < 0 || xx >= WW) continue;
            int q = (b << 12) + (yy << 6) + xx;
            g += g_x[q * 2 + 0] * __ldg(convw + (u * 7 + vv) * 2 + 0)
               + g_x[q * 2 + 1] * __ldg(convw + (u * 7 + vv) * 2 + 1);
        }
    }
    g_sig[idx] = 1.f / (1.f + __expf(-g));
}

// ---------------- KD: fused attention (f32x2, 2 rows/thread) - single wave ----------------
__global__ void __launch_bounds__(128, 4) kD_attn() {
    __shared__ ulonglong2 swn[128 * 5];  // key dim-pairs
    __shared__ ulonglong2 sxe[128 * 3];  // tap pairs (t0,t1)..(t8,1.0)
    __shared__ int s_win;
    int nneed = g_counts[1];
    int x = blockIdx.x, b = blockIdx.y, s = blockIdx.z;
    if (x * ROWS_PB >= nneed) return;
    int nvalid = g_counts[0];
    int chunk = (nvalid + SPLITS - 1) / SPLITS;
    int v0 = s * chunk;
    int v1 = min(v0 + chunk, nvalid);
    int t = threadIdx.x;
    int r0 = x * ROWS_PB + t;
    int r1 = r0 + 128;
    bool act0 = r0 < nneed, act1 = r1 < nneed;

    ull qA[9], qB[9];
    ull initA, initB;
    {
        int n = g_need[r0];
        const ulonglong2* qp = (const ulonglong2*)(g_xfq + (size_t)((b << 12) + n) * 20);
        ulonglong2 a_ = qp[0], b_ = qp[1], c_ = qp[2], d_ = qp[3], e_ = qp[4];
        qA[0] = a_.x; qA[1] = a_.y; qA[2] = b_.x; qA[3] = b_.y; qA[4] = c_.x;
        qA[5] = c_.y; qA[6] = d_.x; qA[7] = d_.y; qA[8] = e_.x;
        initA = pk2(-g_M[(b << 12) + n], 0.f);   // fold -M2 into the dot
    }
    {
        int n = g_need[r1];
        const ulonglong2* qp = (const ulonglong2*)(g_xfq + (size_t)((b << 12) + n) * 20);
        ulonglong2 a_ = qp[0], b_ = qp[1], c_ = qp[2], d_ = qp[3], e_ = qp[4];
        qB[0] = a_.x; qB[1] = a_.y; qB[2] = b_.x; qB[3] = b_.y; qB[4] = c_.x;
        qB[5] = c_.y; qB[6] = d_.x; qB[7] = d_.y; qB[8] = e_.x;
        initB = pk2(-g_M[(b << 12) + n], 0.f);
    }
    ull z = pk2(0.f, 0.f);
    ull aA0 = z, aA1 = z, aA2 = z, aA3 = z, aA4 = z;
    ull aB0 = z, aB1 = z, aB2 = z, aB3 = z, aB4 = z;

    for (int base = v0; base < v1; base += 128) {
        int cnt = min(128, v1 - base);
        __syncthreads();
        if (t < cnt) {
            const ulonglong2* srcw = (const ulonglong2*)(g_wn + (size_t)((b << 12) + base + t) * 20);
            #pragma unroll
            for (int w = 0; w < 5; w++) swn[t * 5 + w] = srcw[w];
            const ulonglong2* srcx = (const ulonglong2*)(g_xfe + (size_t)((b << 12) + base + t) * 12);
            #pragma unroll
            for (int w = 0; w < 3; w++) sxe[t * 3 + w] = srcx[w];
        }
        __syncthreads();
        for (int j = 0; j < cnt; j++) {
            ulonglong2 wa = swn[j * 5], wb = swn[j * 5 + 1], wc = swn[j * 5 + 2], wd = swn[j * 5 + 3];
            ull w8 = swn[j * 5 + 4].x;
            // row A: two independent chains, -M2 pre-folded
            ull m0 = f2fma(qA[0], wa.x, initA);
            ull m1 = f2mul(qA[1], wa.y);
            m0 = f2fma(qA[2], wb.x, m0);
            m1 = f2fma(qA[3], wb.y, m1);
            m0 = f2fma(qA[4], wc.x, m0);
            m1 = f2fma(qA[5], wc.y, m1);
            m0 = f2fma(qA[6], wd.x, m0);
            m1 = f2fma(qA[7], wd.y, m1);
            m0 = f2fma(qA[8], w8, m0);
            // row B
            ull n0 = f2fma(qB[0], wa.x, initB);
            ull n1 = f2mul(qB[1], wa.y);
            n0 = f2fma(qB[2], wb.x, n0);
            n1 = f2fma(qB[3], wb.y, n1);
            n0 = f2fma(qB[4], wc.x, n0);
            n1 = f2fma(qB[5], wc.y, n1);
            n0 = f2fma(qB[6], wd.x, n0);
            n1 = f2fma(qB[7], wd.y, n1);
            n0 = f2fma(qB[8], w8, n0);
            ull sa = f2add(m0, m1);
            ull sb = f2add(n0, n1);
            float alo, ahi, blo, bhi;
            upk(sa, alo, ahi);
            upk(sb, blo, bhi);
            float eA = ex2f(alo + ahi);          // score - M2 <= 0 always (||wn||<=1)
            float eB = ex2f(blo + bhi);
            ull eeA = pk2(eA, eA);
            ull eeB = pk2(eB, eB);
            ulonglong2 xa = sxe[j * 3], xb = sxe[j * 3 + 1], xc = sxe[j * 3 + 2];
            aA0 = f2fma(eeA, xa.x, aA0);  aB0 = f2fma(eeB, xa.x, aB0);
            aA1 = f2fma(eeA, xa.y, aA1);  aB1 = f2fma(eeB, xa.y, aB1);
            aA2 = f2fma(eeA, xb.x, aA2);  aB2 = f2fma(eeB, xb.x, aB2);
            aA3 = f2fma(eeA, xb.y, aA3);  aB3 = f2fma(eeB, xb.y, aB3);
            aA4 = f2fma(eeA, xc.x, aA4);  aB4 = f2fma(eeB, xc.x, aB4);  // (t8,1.0)->(acc8,l)
        }
    }
    if (act0) {
        ull* pa = g_pa + ((size_t)((b * SPLITS + s) << 12) + r0) * 5;
        pa[0] = aA0; pa[1] = aA1; pa[2] = aA2; pa[3] = aA3; pa[4] = aA4;
    }
    if (act1) {
        ull* pa = g_pa + ((size_t)((b * SPLITS + s) << 12) + r1) * 5;
        pa[0] = aB0; pa[1] = aB1; pa[2] = aB2; pa[3] = aB3; pa[4] = aB4;
    }
    // split-arrival; last block of this (b,x) group reduces (fixed s order => deterministic)
    __syncthreads();
    if (t == 0) {
        __threadfence();
        int old = atomicAdd(&g_cnt[b * GX + x], 1);
        s_win = (old == SPLITS - 1) ? 1 : 0;
        if (s_win) g_cnt[b * GX + x] = 0;        // reset for next graph replay
    }
    __syncthreads();
    if (s_win) {
        ull z2 = pk2(0.f, 0.f);
        #pragma unroll
        for (int rr = 0; rr < 2; rr++) {
            int r = (rr == 0) ? r0 : r1;
            bool act = (rr == 0) ? act0 : act1;
            if (!act) continue;
            int n = g_need[r];
            float M2v = g_M[(b << 12) + n];
            ull c0 = z2, c1 = z2, c2 = z2, c3 = z2;
            ull c4 = pk2(0.f, (float)(PP - nvalid) * ex2f(-M2v));  // masked keys' denominator
            #pragma unroll
            for (int ss2 = 0; ss2 < SPLITS; ss2++) {
                const ull* pa = g_pa + ((size_t)((b * SPLITS + ss2) << 12) + r) * 5;
                c0 = f2add(c0, pa[0]);
                c1 = f2add(c1, pa[1]);
                c2 = f2add(c2, pa[2]);
                c3 = f2add(c3, pa[3]);
                c4 = f2add(c4, pa[4]);
            }
            float f[10];
            upk(c0, f[0], f[1]);
            upk(c1, f[2], f[3]);
            upk(c2, f[4], f[5]);
            upk(c3, f[6], f[7]);
            upk(c4, f[8], f[9]);
            float rl = 1.f / f[9];
            float* dst = g_tmp9 + (size_t)((b << 12) + n) * 9;
            #pragma unroll
            for (int k = 0; k < 9; k++) dst[k] = f[k] * rl;
        }
    }
}

// ---------------- KF: transpose-conv gather + final elementwise (2 pixels/warp) ----------------
__global__ void kF_final(const float* __restrict__ inp, const float* __restrict__ mask,
                         const float* __restrict__ bias, float* __restrict__ out) {
    int t = threadIdx.x;
    int lane = t & 31;
    int sub = lane & 15;
    int gw = blockIdx.x * 16 + (t >> 5) * 2 + (lane >> 4);   // pixel index b*4096+p
    int p = gw & 4095, b = gw >> 12, y = p >> 6, x = p & 63;
    float mv = mask[p];
    float ysum = 0.f;
    if (mv < 0.5f && sub < 9) {
        int kh = sub / 3, kw = sub % 3;
        int ny = y - (kh - 1), nx = x - (kw - 1);
        if (ny >= 0 && ny < HH && nx >= 0 && nx < WW)
            ysum = g_tmp9[(size_t)((b << 12) + (ny << 6) + nx) * 9 + sub];
    }
    #pragma unroll
    for (int o = 8; o; o >>= 1)
        ysum += __shfl_xor_sync(0xffffffffu, ysum, o);
    float sg = g_sig[gw];
    float yb = ysum * 0.25f;
    float w = 1.0f - mv;
    int base4 = gw << 5;
    int pbase4 = p << 5;
    #pragma unroll
    for (int k = 0; k < 2; k++) {
        int c4 = sub + k * 16;
        float4 iv = ((const float4*)inp)[base4 + c4];
        float4 bv = ((const float4*)bias)[pbase4 + c4];
        float4 o4;
        o4.x = sg * (iv.x + (yb + bv.x) * w);
        o4.y = sg * (iv.y + (yb + bv.y) * w);
        o4.z = sg * (iv.z + (yb + bv.z) * w);
        o4.w = sg * (iv.w + (yb + bv.w) * w);
        ((float4*)out)[base4 + c4] = o4;
    }
}

// ---------------- launch ----------------
extern "C" void kernel_launch(void* const* d_in, const int* in_sizes, int n_in,
                              void* d_out, int out_size) {
    const float* inp   = (const float*)d_in[0];
    const float* mask  = (const float*)d_in[1];
    const float* bias  = (const float*)d_in[2];
    const float* convw = (const float*)d_in[3];
    float* out = (float*)d_out;

    kA<<<1025, 256>>>(inp, mask);
    kB_patches<<<(BB * PP) / 256, 256>>>(convw);
    dim3 gD(GX, BB, SPLITS);
    kD_attn<<<gD, 128>>>();
    kF_final<<<(BB * PP) / 16, 256>>>(inp, mask, bias, out);
}

// round 12
// speedup vs baseline: 1.1606x; 1.1606x over previous
#include <cuda_runtime.h>
#include <math.h>

#define BB 4
#define HH 64
#define WW 64
#define CC 128
#define PP 4096
#define SPLITS 18
#define GX 16
#define ROWS_PB 256
#define LOG2E 1.44269504088896340736f

typedef unsigned long long ull;

// ---------------- static scratch ----------------
__device__ float g_x[BB * PP * 2];          // per-pixel (mean, max)
__device__ float g_xfq[BB * PP * 20];       // queries pre-scaled by LOG2E, 18+2 pad
__device__ float g_M[BB * PP];              // M2 = patch L2 norm * LOG2E
__device__ float g_wn[BB * PP * 20];        // compacted normalized keys, 18+2 pad
__device__ float g_xfe[BB * PP * 12];       // compacted taps [t0..t8, 1.0, 0, 0]
__device__ float g_sig[BB * PP];            // sigmoid(gate conv)
__device__ int   g_vrank[PP];               // pixel -> compacted key index (or -1)
__device__ int   g_need[PP];
__device__ int   g_counts[2];               // [0]=n_valid, [1]=n_need
__device__ ull   g_pa[(size_t)BB * SPLITS * PP * 5];  // packed split partials (9 taps + l)
__device__ float g_tmp9[BB * PP * 9];
__device__ int   g_cnt[BB * GX];            // split arrival counters (self-resetting)

// ---- packed f32x2 helpers ----
__device__ __forceinline__ ull pk2(float lo, float hi) {
    ull r; asm("mov.b64 %0, {%1, %2};" : "=l"(r) : "f"(lo), "f"(hi)); return r;
}
__device__ __forceinline__ void upk(ull v, float& lo, float& hi) {
    asm("mov.b64 {%0, %1}, %2;" : "=f"(lo), "=f"(hi) : "l"(v));
}
__device__ __forceinline__ ull f2fma(ull a, ull b, ull c) {
    ull d; asm("fma.rn.f32x2 %0, %1, %2, %3;" : "=l"(d) : "l"(a), "l"(b), "l"(c)); return d;
}
__device__ __forceinline__ ull f2mul(ull a, ull b) {
    ull d; asm("mul.rn.f32x2 %0, %1, %2;" : "=l"(d) : "l"(a), "l"(b)); return d;
}
__device__ __forceinline__ ull f2add(ull a, ull b) {
    ull d; asm("add.rn.f32x2 %0, %1, %2;" : "=l"(d) : "l"(a), "l"(b)); return d;
}
__device__ __forceinline__ float ex2f(float x) {
    float r; asm("ex2.approx.f32 %0, %1;" : "=f"(r) : "f"(x)); return r;
}

// ---------------- KA: mean/max (blocks 0..1023, 2 pixels/warp) + compaction (block 1024) ----------------
__global__ void kA(const float* __restrict__ inp, const float* __restrict__ mask) {
    __shared__ int wv[8], wn_[8];
    if (blockIdx.x == 1024) {
        int t = threadIdx.x;
        int lane = t & 31, wid = t >> 5;
        unsigned fv = 0, fn = 0;
        int cv = 0, cn = 0;
        int base_p = t * 16;
        for (int i = 0; i < 16; i++) {
            int p = base_p + i, y = p >> 6, x = p & 63;
            int allone = 1, anyz = 0;
            #pragma unroll
            for (int dy = -1; dy <= 1; dy++)
                #pragma unroll
                for (int dx = -1; dx <= 1; dx++) {
                    int yy = y + dy, xx = x + dx;
                    if (yy < 0 || yy >= HH || xx < 0 || xx >= WW) {
                        allone = 0;
                    } else {
                        float mv = mask[(yy << 6) + xx];
                        if (mv < 0.5f) { allone = 0; anyz = 1; }
                    }
                }
            if (allone) { fv |= (1u << i); cv++; }
            if (anyz)   { fn |= (1u << i); cn++; }
        }
        int iv = cv, inn = cn;
        #pragma unroll
        for (int o = 1; o < 32; o <<= 1) {
            int a = __shfl_up_sync(0xffffffffu, iv, o);
            int b = __shfl_up_sync(0xffffffffu, inn, o);
            if (lane >= o) { iv += a; inn += b; }
        }
        if (lane == 31) { wv[wid] = iv; wn_[wid] = inn; }
        __syncthreads();
        int bv = 0, bn = 0;
        for (int i = 0; i < wid; i++) { bv += wv[i]; bn += wn_[i]; }
        int offv = bv + iv - cv;
        int offn = bn + inn - cn;
        for (int i = 0; i < 16; i++) {
            int p = base_p + i;
            if (fv & (1u << i)) g_vrank[p] = offv++;
            else                g_vrank[p] = -1;
            if (fn & (1u << i)) g_need[offn++] = p;
        }
        if (t == 255) { g_counts[0] = bv + iv; g_counts[1] = bn + inn; }
        return;
    }
    // 2 pixels per warp: 16-lane group each
    int lane = threadIdx.x & 31;
    int pix = blockIdx.x * 16 + (threadIdx.x >> 5) * 2 + (lane >> 4);
    int sub = lane & 15;
    const float4* base = (const float4*)(inp + (size_t)pix * CC);
    float4 v1 = base[sub];
    float4 v2 = base[sub + 16];
    float s = ((v1.x + v1.y) + (v1.z + v1.w)) + ((v2.x + v2.y) + (v2.z + v2.w));
    float m = fmaxf(fmaxf(fmaxf(v1.x, v1.y), fmaxf(v1.z, v1.w)),
                    fmaxf(fmaxf(v2.x, v2.y), fmaxf(v2.z, v2.w)));
    #pragma unroll
    for (int o = 8; o; o >>= 1) {
        s += __shfl_xor_sync(0xffffffffu, s, o);
        m = fmaxf(m, __shfl_xor_sync(0xffffffffu, m, o));
    }
    if (sub == 0) {
        g_x[pix * 2 + 0] = s * (1.0f / 128.0f);
        g_x[pix * 2 + 1] = m;
    }
}

// ---------------- KB: patch vectors + norms + compacted keys/values + gate conv ----------------
__global__ void kB_patches(const float* __restrict__ convw) {
    int idx = blockIdx.x * blockDim.x + threadIdx.x;   // BB*PP
    if (idx >= BB * PP) return;
    int p = idx & 4095, y = p >> 6, x = p & 63;
    int b = idx >> 12;
    float v[18];
    float ss = 0.f;
    int j = 0;
    #pragma unroll
    for (int kh = 0; kh < 3; kh++)
        #pragma unroll
        for (int kw = 0; kw < 3; kw++) {
            int yy = y + kh - 1, xx = x + kw - 1;
            float a = 0.f, c1 = 0.f;
            if (yy >= 0 && yy < HH && xx >= 0 && xx < WW) {
                int q = (b << 12) + (yy << 6) + xx;
                a  = g_x[q * 2 + 0];
                c1 = g_x[q * 2 + 1];
            }
            v[j] = a; v[j + 1] = c1;
            ss += a * a + c1 * c1;
            j += 2;
        }
    float Mn = sqrtf(ss);
    // query: pre-scaled by LOG2E
    float* dst = g_xfq + (size_t)idx * 20;
    #pragma unroll
    for (int i = 0; i < 18; i++) dst[i] = v[i] * LOG2E;
    dst[18] = 0.f; dst[19] = 0.f;
    g_M[idx] = Mn * LOG2E;
    // key/value if this pixel is a fully-valid patch
    int vr = g_vrank[p];
    if (vr >= 0) {
        float rn = 1.f / fmaxf(Mn, 1e-4f);
        float* dw = g_wn + (size_t)((b << 12) + vr) * 20;
        #pragma unroll
        for (int i = 0; i < 18; i++) dw[i] = v[i] * rn;
        dw[18] = 0.f; dw[19] = 0.f;
        float* de = g_xfe + (size_t)((b << 12) + vr) * 12;
        #pragma unroll
        for (int k = 0; k < 9; k++) de[k] = v[2 * k];
        de[9] = 1.0f;          // synthetic tap: accumulates the softmax denominator
        de[10] = 0.f; de[11] = 0.f;
    }
    // 7x7x2 gate conv + sigmoid (independent of attention)
    float g = 0.f;
    #pragma unroll
    for (int u = 0; u < 7; u++) {
        int yy = y + u - 3;
        if (yy < 0 || yy >= HH) continue;
        #pragma unroll
        for (int vv = 0; vv < 7; vv++) {
            int xx = x + vv - 3;
            if (xx < 0 || xx >= WW) continue;
            int q = (b << 12) + (yy << 6) + xx;
            g += g_x[q * 2 + 0] * __ldg(convw + (u * 7 + vv) * 2 + 0)
               + g_x[q * 2 + 1] * __ldg(convw + (u * 7 + vv) * 2 + 1);
        }
    }
    g_sig[idx] = 1.f / (1.f + __expf(-g));
}

// ---------------- KD: fused attention (f32x2, 2 rows/thread), deep split-K single wave ----------------
__global__ void __launch_bounds__(128, 5) kD_attn() {
    __shared__ ulonglong2 swn[128 * 5];  // key dim-pairs
    __shared__ ulonglong2 sxe[128 * 3];  // tap pairs (t0,t1)..(t8,1.0)
    __shared__ int s_win;
    int nneed = g_counts[1];
    int x = blockIdx.x, b = blockIdx.y, s = blockIdx.z;
    if (x * ROWS_PB >= nneed) return;
    int nvalid = g_counts[0];
    int chunk = (nvalid + SPLITS - 1) / SPLITS;
    int v0 = s * chunk;
    int v1 = min(v0 + chunk, nvalid);
    int t = threadIdx.x;
    int r0 = x * ROWS_PB + t;
    int r1 = r0 + 128;
    bool act0 = r0 < nneed, act1 = r1 < nneed;

    ull qA[9], qB[9];
    ull initA, initB;
    {
        int n = g_need[r0];
        const ulonglong2* qp = (const ulonglong2*)(g_xfq + (size_t)((b << 12) + n) * 20);
        ulonglong2 a_ = qp[0], b_ = qp[1], c_ = qp[2], d_ = qp[3], e_ = qp[4];
        qA[0] = a_.x; qA[1] = a_.y; qA[2] = b_.x; qA[3] = b_.y; qA[4] = c_.x;
        qA[5] = c_.y; qA[6] = d_.x; qA[7] = d_.y; qA[8] = e_.x;
        initA = pk2(-g_M[(b << 12) + n], 0.f);   // fold -M2 into the dot
    }
    {
        int n = g_need[r1];
        const ulonglong2* qp = (const ulonglong2*)(g_xfq + (size_t)((b << 12) + n) * 20);
        ulonglong2 a_ = qp[0], b_ = qp[1], c_ = qp[2], d_ = qp[3], e_ = qp[4];
        qB[0] = a_.x; qB[1] = a_.y; qB[2] = b_.x; qB[3] = b_.y; qB[4] = c_.x;
        qB[5] = c_.y; qB[6] = d_.x; qB[7] = d_.y; qB[8] = e_.x;
        initB = pk2(-g_M[(b << 12) + n], 0.f);
    }
    ull z = pk2(0.f, 0.f);
    ull aA0 = z, aA1 = z, aA2 = z, aA3 = z, aA4 = z;
    ull aB0 = z, aB1 = z, aB2 = z, aB3 = z, aB4 = z;

    for (int base = v0; base < v1; base += 128) {
        int cnt = min(128, v1 - base);
        __syncthreads();
        if (t < cnt) {
            const ulonglong2* srcw = (const ulonglong2*)(g_wn + (size_t)((b << 12) + base + t) * 20);
            #pragma unroll
            for (int w = 0; w < 5; w++) swn[t * 5 + w] = srcw[w];
            const ulonglong2* srcx = (const ulonglong2*)(g_xfe + (size_t)((b << 12) + base + t) * 12);
            #pragma unroll
            for (int w = 0; w < 3; w++) sxe[t * 3 + w] = srcx[w];
        }
        __syncthreads();
        for (int j = 0; j < cnt; j++) {
            ulonglong2 wa = swn[j * 5], wb = swn[j * 5 + 1], wc = swn[j * 5 + 2], wd = swn[j * 5 + 3];
            ull w8 = swn[j * 5 + 4].x;
            // row A: two independent chains, -M2 pre-folded
            ull m0 = f2fma(qA[0], wa.x, initA);
            ull m1 = f2mul(qA[1], wa.y);
            m0 = f2fma(qA[2], wb.x, m0);
            m1 = f2fma(qA[3], wb.y, m1);
            m0 = f2fma(qA[4], wc.x, m0);
            m1 = f2fma(qA[5], wc.y, m1);
            m0 = f2fma(qA[6], wd.x, m0);
            m1 = f2fma(qA[7], wd.y, m1);
            m0 = f2fma(qA[8], w8, m0);
            // row B
            ull n0 = f2fma(qB[0], wa.x, initB);
            ull n1 = f2mul(qB[1], wa.y);
            n0 = f2fma(qB[2], wb.x, n0);
            n1 = f2fma(qB[3], wb.y, n1);
            n0 = f2fma(qB[4], wc.x, n0);
            n1 = f2fma(qB[5], wc.y, n1);
            n0 = f2fma(qB[6], wd.x, n0);
            n1 = f2fma(qB[7], wd.y, n1);
            n0 = f2fma(qB[8], w8, n0);
            ull sa = f2add(m0, m1);
            ull sb = f2add(n0, n1);
            float alo, ahi, blo, bhi;
            upk(sa, alo, ahi);
            upk(sb, blo, bhi);
            float eA = ex2f(alo + ahi);          // score - M2 <= 0 always (||wn||<=1)
            float eB = ex2f(blo + bhi);
            ull eeA = pk2(eA, eA);
            ull eeB = pk2(eB, eB);
            ulonglong2 xa = sxe[j * 3], xb = sxe[j * 3 + 1], xc = sxe[j * 3 + 2];
            aA0 = f2fma(eeA, xa.x, aA0);  aB0 = f2fma(eeB, xa.x, aB0);
            aA1 = f2fma(eeA, xa.y, aA1);  aB1 = f2fma(eeB, xa.y, aB1);
            aA2 = f2fma(eeA, xb.x, aA2);  aB2 = f2fma(eeB, xb.x, aB2);
            aA3 = f2fma(eeA, xb.y, aA3);  aB3 = f2fma(eeB, xb.y, aB3);
            aA4 = f2fma(eeA, xc.x, aA4);  aB4 = f2fma(eeB, xc.x, aB4);  // (t8,1.0)->(acc8,l)
        }
    }
    if (act0) {
        ull* pa = g_pa + ((size_t)((b * SPLITS + s) << 12) + r0) * 5;
        pa[0] = aA0; pa[1] = aA1; pa[2] = aA2; pa[3] = aA3; pa[4] = aA4;
    }
    if (act1) {
        ull* pa = g_pa + ((size_t)((b * SPLITS + s) << 12) + r1) * 5;
        pa[0] = aB0; pa[1] = aB1; pa[2] = aB2; pa[3] = aB3; pa[4] = aB4;
    }
    // split-arrival; last block of this (b,x) group reduces (fixed s order => deterministic)
    __syncthreads();
    if (t == 0) {
        __threadfence();
        int old = atomicAdd(&g_cnt[b * GX + x], 1);
        s_win = (old == SPLITS - 1) ? 1 : 0;
        if (s_win) g_cnt[b * GX + x] = 0;        // reset for next graph replay
    }
    __syncthreads();
    if (s_win) {
        ull z2 = pk2(0.f, 0.f);
        #pragma unroll
        for (int rr = 0; rr < 2; rr++) {
            int r = (rr == 0) ? r0 : r1;
            bool act = (rr == 0) ? act0 : act1;
            if (!act) continue;
            int n = g_need[r];
            float M2v = g_M[(b << 12) + n];
            ull c0 = z2, c1 = z2, c2 = z2, c3 = z2;
            ull c4 = pk2(0.f, (float)(PP - nvalid) * ex2f(-M2v));  // masked keys' denominator
            #pragma unroll
            for (int ss2 = 0; ss2 < SPLITS; ss2++) {
                const ull* pa = g_pa + ((size_t)((b * SPLITS + ss2) << 12) + r) * 5;
                c0 = f2add(c0, pa[0]);
                c1 = f2add(c1, pa[1]);
                c2 = f2add(c2, pa[2]);
                c3 = f2add(c3, pa[3]);
                c4 = f2add(c4, pa[4]);
            }
            float f[10];
            upk(c0, f[0], f[1]);
            upk(c1, f[2], f[3]);
            upk(c2, f[4], f[5]);
            upk(c3, f[6], f[7]);
            upk(c4, f[8], f[9]);
            float rl = 1.f / f[9];
            float* dst = g_tmp9 + (size_t)((b << 12) + n) * 9;
            #pragma unroll
            for (int k = 0; k < 9; k++) dst[k] = f[k] * rl;
        }
    }
}

// ---------------- KF: transpose-conv gather + final elementwise (2 pixels/warp) ----------------
__global__ void kF_final(const float* __restrict__ inp, const float* __restrict__ mask,
                         const float* __restrict__ bias, float* __restrict__ out) {
    int t = threadIdx.x;
    int lane = t & 31;
    int sub = lane & 15;
    int gw = blockIdx.x * 16 + (t >> 5) * 2 + (lane >> 4);   // pixel index b*4096+p
    int p = gw & 4095, b = gw >> 12, y = p >> 6, x = p & 63;
    float mv = mask[p];
    float ysum = 0.f;
    if (mv < 0.5f && sub < 9) {
        int kh = sub / 3, kw = sub % 3;
        int ny = y - (kh - 1), nx = x - (kw - 1);
        if (ny >= 0 && ny < HH && nx >= 0 && nx < WW)
            ysum = g_tmp9[(size_t)((b << 12) + (ny << 6) + nx) * 9 + sub];
    }
    #pragma unroll
    for (int o = 8; o; o >>= 1)
        ysum += __shfl_xor_sync(0xffffffffu, ysum, o);
    float sg = g_sig[gw];
    float yb = ysum * 0.25f;
    float w = 1.0f - mv;
    int base4 = gw << 5;
    int pbase4 = p << 5;
    #pragma unroll
    for (int k = 0; k < 2; k++) {
        int c4 = sub + k * 16;
        float4 iv = ((const float4*)inp)[base4 + c4];
        float4 bv = ((const float4*)bias)[pbase4 + c4];
        float4 o4;
        o4.x = sg * (iv.x + (yb + bv.x) * w);
        o4.y = sg * (iv.y + (yb + bv.y) * w);
        o4.z = sg * (iv.z + (yb + bv.z) * w);
        o4.w = sg * (iv.w + (yb + bv.w) * w);
        ((float4*)out)[base4 + c4] = o4;
    }
}

// ---------------- launch ----------------
extern "C" void kernel_launch(void* const* d_in, const int* in_sizes, int n_in,
                              void* d_out, int out_size) {
    const float* inp   = (const float*)d_in[0];
    const float* mask  = (const float*)d_in[1];
    const float* bias  = (const float*)d_in[2];
    const float* convw = (const float*)d_in[3];
    float* out = (float*)d_out;

    kA<<<1025, 256>>>(inp, mask);
    kB_patches<<<(BB * PP) / 256, 256>>>(convw);
    dim3 gD(GX, BB, SPLITS);
    kD_attn<<<gD, 128>>>();
    kF_final<<<(BB * PP) / 16, 256>>>(inp, mask, bias, out);
}

// round 14
// speedup vs baseline: 1.1667x; 1.0052x over previous
#include <cuda_runtime.h>
#include <math.h>

#define BB 4
#define HH 64
#define WW 64
#define CC 128
#define PP 4096
#define SPLITS 18
#define GX 16
#define ROWS_PB 256
#define LOG2E 1.44269504088896340736f

typedef unsigned long long ull;

// ---------------- static scratch ----------------
__device__ float g_x[BB * PP * 2];          // per-pixel (mean, max)
__device__ float g_xfq[BB * PP * 20];       // queries pre-scaled by LOG2E, 18+2 pad
__device__ float g_M[BB * PP];              // M2 = patch L2 norm * LOG2E
__device__ float g_wn[BB * PP * 20];        // compacted normalized keys, 18+2 pad
__device__ float g_xfe[BB * PP * 12];       // compacted taps [t0..t8, 1.0, 0, 0]
__device__ float g_sig[BB * PP];            // sigmoid(gate conv)
__device__ int   g_vrank[PP];               // pixel -> compacted key index (or -1)
__device__ int   g_need[PP];
__device__ int   g_counts[2];               // [0]=n_valid, [1]=n_need
__device__ ull   g_pa[(size_t)BB * SPLITS * PP * 5];  // packed split partials (9 taps + l)
__device__ float g_tmp9[BB * PP * 9];
__device__ int   g_cnt[BB * GX];            // split arrival counters (self-resetting)

// ---- packed f32x2 helpers ----
__device__ __forceinline__ ull pk2(float lo, float hi) {
    ull r; asm("mov.b64 %0, {%1, %2};" : "=l"(r) : "f"(lo), "f"(hi)); return r;
}
__device__ __forceinline__ void upk(ull v, float& lo, float& hi) {
    asm("mov.b64 {%0, %1}, %2;" : "=f"(lo), "=f"(hi) : "l"(v));
}
__device__ __forceinline__ ull f2fma(ull a, ull b, ull c) {
    ull d; asm("fma.rn.f32x2 %0, %1, %2, %3;" : "=l"(d) : "l"(a), "l"(b), "l"(c)); return d;
}
__device__ __forceinline__ ull f2mul(ull a, ull b) {
    ull d; asm("mul.rn.f32x2 %0, %1, %2;" : "=l"(d) : "l"(a), "l"(b)); return d;
}
__device__ __forceinline__ ull f2add(ull a, ull b) {
    ull d; asm("add.rn.f32x2 %0, %1, %2;" : "=l"(d) : "l"(a), "l"(b)); return d;
}
__device__ __forceinline__ float ex2f(float x) {
    float r; asm("ex2.approx.f32 %0, %1;" : "=f"(r) : "f"(x)); return r;
}

// ---------------- KA: mean/max (blocks 0..511, 4 pixels/warp, MLP=4) + compaction (block 512) ----------------
__global__ void kA(const float* __restrict__ inp, const float* __restrict__ mask) {
    __shared__ int wv[8], wn_[8];
    if (blockIdx.x == 512) {
        int t = threadIdx.x;
        int lane = t & 31, wid = t >> 5;
        unsigned fv = 0, fn = 0;
        int cv = 0, cn = 0;
        int base_p = t * 16;
        for (int i = 0; i < 16; i++) {
            int p = base_p + i, y = p >> 6, x = p & 63;
            int allone = 1, anyz = 0;
            #pragma unroll
            for (int dy = -1; dy <= 1; dy++)
                #pragma unroll
                for (int dx = -1; dx <= 1; dx++) {
                    int yy = y + dy, xx = x + dx;
                    if (yy < 0 || yy >= HH || xx < 0 || xx >= WW) {
                        allone = 0;
                    } else {
                        float mv = mask[(yy << 6) + xx];
                        if (mv < 0.5f) { allone = 0; anyz = 1; }
                    }
                }
            if (allone) { fv |= (1u << i); cv++; }
            if (anyz)   { fn |= (1u << i); cn++; }
        }
        int iv = cv, inn = cn;
        #pragma unroll
        for (int o = 1; o < 32; o <<= 1) {
            int a = __shfl_up_sync(0xffffffffu, iv, o);
            int b = __shfl_up_sync(0xffffffffu, inn, o);
            if (lane >= o) { iv += a; inn += b; }
        }
        if (lane == 31) { wv[wid] = iv; wn_[wid] = inn; }
        __syncthreads();
        int bv = 0, bn = 0;
        for (int i = 0; i < wid; i++) { bv += wv[i]; bn += wn_[i]; }
        int offv = bv + iv - cv;
        int offn = bn + inn - cn;
        for (int i = 0; i < 16; i++) {
            int p = base_p + i;
            if (fv & (1u << i)) g_vrank[p] = offv++;
            else                g_vrank[p] = -1;
            if (fn & (1u << i)) g_need[offn++] = p;
        }
        if (t == 255) { g_counts[0] = bv + iv; g_counts[1] = bn + inn; }
        return;
    }
    // 4 pixels per warp: 8-lane group each, 4 independent float4 loads per thread
    int lane = threadIdx.x & 31;
    int pix = blockIdx.x * 32 + (threadIdx.x >> 5) * 4 + (lane >> 3);
    int sub = lane & 7;
    const float4* base = (const float4*)(inp + (size_t)pix * CC);
    float4 v0 = base[sub];
    float4 v1 = base[sub + 8];
    float4 v2 = base[sub + 16];
    float4 v3 = base[sub + 24];
    float s = (((v0.x + v0.y) + (v0.z + v0.w)) + ((v1.x + v1.y) + (v1.z + v1.w)))
            + (((v2.x + v2.y) + (v2.z + v2.w)) + ((v3.x + v3.y) + (v3.z + v3.w)));
    float m = fmaxf(
        fmaxf(fmaxf(fmaxf(v0.x, v0.y), fmaxf(v0.z, v0.w)),
              fmaxf(fmaxf(v1.x, v1.y), fmaxf(v1.z, v1.w))),
        fmaxf(fmaxf(fmaxf(v2.x, v2.y), fmaxf(v2.z, v2.w)),
              fmaxf(fmaxf(v3.x, v3.y), fmaxf(v3.z, v3.w))));
    #pragma unroll
    for (int o = 4; o; o >>= 1) {
        s += __shfl_xor_sync(0xffffffffu, s, o);
        m = fmaxf(m, __shfl_xor_sync(0xffffffffu, m, o));
    }
    if (sub == 0) {
        g_x[pix * 2 + 0] = s * (1.0f / 128.0f);
        g_x[pix * 2 + 1] = m;
    }
}

// ---------------- KB: patch vectors + norms + compacted keys/values + gate conv (float2 loads) ----------------
__global__ void kB_patches(const float* __restrict__ convw) {
    int idx = blockIdx.x * blockDim.x + threadIdx.x;   // BB*PP
    if (idx >= BB * PP) return;
    int p = idx & 4095, y = p >> 6, x = p & 63;
    int b = idx >> 12;
    const float2* gx2 = (const float2*)g_x;
    float v[18];
    float ss = 0.f;
    int j = 0;
    #pragma unroll
    for (int kh = 0; kh < 3; kh++)
        #pragma unroll
        for (int kw = 0; kw < 3; kw++) {
            int yy = y + kh - 1, xx = x + kw - 1;
            float a = 0.f, c1 = 0.f;
            if (yy >= 0 && yy < HH && xx >= 0 && xx < WW) {
                float2 gv = gx2[(b << 12) + (yy << 6) + xx];
                a = gv.x; c1 = gv.y;
            }
            v[j] = a; v[j + 1] = c1;
            ss += a * a + c1 * c1;
            j += 2;
        }
    float Mn = sqrtf(ss);
    // query: pre-scaled by LOG2E
    float* dst = g_xfq + (size_t)idx * 20;
    #pragma unroll
    for (int i = 0; i < 18; i++) dst[i] = v[i] * LOG2E;
    dst[18] = 0.f; dst[19] = 0.f;
    g_M[idx] = Mn * LOG2E;
    // key/value if this pixel is a fully-valid patch
    int vr = g_vrank[p];
    if (vr >= 0) {
        float rn = 1.f / fmaxf(Mn, 1e-4f);
        float* dw = g_wn + (size_t)((b << 12) + vr) * 20;
        #pragma unroll
        for (int i = 0; i < 18; i++) dw[i] = v[i] * rn;
        dw[18] = 0.f; dw[19] = 0.f;
        float* de = g_xfe + (size_t)((b << 12) + vr) * 12;
        #pragma unroll
        for (int k = 0; k < 9; k++) de[k] = v[2 * k];
        de[9] = 1.0f;          // synthetic tap: accumulates the softmax denominator
        de[10] = 0.f; de[11] = 0.f;
    }
    // 7x7x2 gate conv + sigmoid (float2 per neighbor)
    float g = 0.f;
    #pragma unroll
    for (int u = 0; u < 7; u++) {
        int yy = y + u - 3;
        if (yy < 0 || yy >= HH) continue;
        #pragma unroll
        for (int vv = 0; vv < 7; vv++) {
            int xx = x + vv - 3;
            if (xx < 0 || xx >= WW) continue;
            float2 gv = gx2[(b << 12) + (yy << 6) + xx];
            g += gv.x * __ldg(convw + (u * 7 + vv) * 2 + 0)
               + gv.y * __ldg(convw + (u * 7 + vv) * 2 + 1);
        }
    }
    g_sig[idx] = 1.f / (1.f + __expf(-g));
}

// ---------------- KD: fused attention (f32x2, 2 rows/thread), deep split-K single wave ----------------
__global__ void __launch_bounds__(128, 5) kD_attn() {
    __shared__ ulonglong2 swn[128 * 5];  // key dim-pairs
    __shared__ ulonglong2 sxe[128 * 3];  // tap pairs (t0,t1)..(t8,1.0)
    __shared__ int s_win;
    int nneed = g_counts[1];
    int x = blockIdx.x, b = blockIdx.y, s = blockIdx.z;
    if (x * ROWS_PB >= nneed) return;
    int nvalid = g_counts[0];
    int chunk = (nvalid + SPLITS - 1) / SPLITS;
    int v0 = s * chunk;
    int v1 = min(v0 + chunk, nvalid);
    int t = threadIdx.x;
    int r0 = x * ROWS_PB + t;
    int r1 = r0 + 128;
    bool act0 = r0 < nneed, act1 = r1 < nneed;

    ull qA[9], qB[9];
    ull initA, initB;
    {
        int n = g_need[r0];
        const ulonglong2* qp = (const ulonglong2*)(g_xfq + (size_t)((b << 12) + n) * 20);
        ulonglong2 a_ = qp[0], b_ = qp[1], c_ = qp[2], d_ = qp[3], e_ = qp[4];
        qA[0] = a_.x; qA[1] = a_.y; qA[2] = b_.x; qA[3] = b_.y; qA[4] = c_.x;
        qA[5] = c_.y; qA[6] = d_.x; qA[7] = d_.y; qA[8] = e_.x;
        initA = pk2(-g_M[(b << 12) + n], 0.f);   // fold -M2 into the dot
    }
    {
        int n = g_need[r1];
        const ulonglong2* qp = (const ulonglong2*)(g_xfq + (size_t)((b << 12) + n) * 20);
        ulonglong2 a_ = qp[0], b_ = qp[1], c_ = qp[2], d_ = qp[3], e_ = qp[4];
        qB[0] = a_.x; qB[1] = a_.y; qB[2] = b_.x; qB[3] = b_.y; qB[4] = c_.x;
        qB[5] = c_.y; qB[6] = d_.x; qB[7] = d_.y; qB[8] = e_.x;
        initB = pk2(-g_M[(b << 12) + n], 0.f);
    }
    ull z = pk2(0.f, 0.f);
    ull aA0 = z, aA1 = z, aA2 = z, aA3 = z, aA4 = z;
    ull aB0 = z, aB1 = z, aB2 = z, aB3 = z, aB4 = z;

    for (int base = v0; base < v1; base += 128) {
        int cnt = min(128, v1 - base);
        __syncthreads();
        if (t < cnt) {
            const ulonglong2* srcw = (const ulonglong2*)(g_wn + (size_t)((b << 12) + base + t) * 20);
            #pragma unroll
            for (int w = 0; w < 5; w++) swn[t * 5 + w] = srcw[w];
            const ulonglong2* srcx = (const ulonglong2*)(g_xfe + (size_t)((b << 12) + base + t) * 12);
            #pragma unroll
            for (int w = 0; w < 3; w++) sxe[t * 3 + w] = srcx[w];
        }
        __syncthreads();
        for (int j = 0; j < cnt; j++) {
            ulonglong2 wa = swn[j * 5], wb = swn[j * 5 + 1], wc = swn[j * 5 + 2], wd = swn[j * 5 + 3];
            ull w8 = swn[j * 5 + 4].x;
            // row A: two independent chains, -M2 pre-folded
            ull m0 = f2fma(qA[0], wa.x, initA);
            ull m1 = f2mul(qA[1], wa.y);
            m0 = f2fma(qA[2], wb.x, m0);
            m1 = f2fma(qA[3], wb.y, m1);
            m0 = f2fma(qA[4], wc.x, m0);
            m1 = f2fma(qA[5], wc.y, m1);
            m0 = f2fma(qA[6], wd.x, m0);
            m1 = f2fma(qA[7], wd.y, m1);
            m0 = f2fma(qA[8], w8, m0);
            // row B
            ull n0 = f2fma(qB[0], wa.x, initB);
            ull n1 = f2mul(qB[1], wa.y);
            n0 = f2fma(qB[2], wb.x, n0);
            n1 = f2fma(qB[3], wb.y, n1);
            n0 = f2fma(qB[4], wc.x, n0);
            n1 = f2fma(qB[5], wc.y, n1);
            n0 = f2fma(qB[6], wd.x, n0);
            n1 = f2fma(qB[7], wd.y, n1);
            n0 = f2fma(qB[8], w8, n0);
            ull sa = f2add(m0, m1);
            ull sb = f2add(n0, n1);
            float alo, ahi, blo, bhi;
            upk(sa, alo, ahi);
            upk(sb, blo, bhi);
            float eA = ex2f(alo + ahi);          // score - M2 <= 0 always (||wn||<=1)
            float eB = ex2f(blo + bhi);
            ull eeA = pk2(eA, eA);
            ull eeB = pk2(eB, eB);
            ulonglong2 xa = sxe[j * 3], xb = sxe[j * 3 + 1], xc = sxe[j * 3 + 2];
            aA0 = f2fma(eeA, xa.x, aA0);  aB0 = f2fma(eeB, xa.x, aB0);
            aA1 = f2fma(eeA, xa.y, aA1);  aB1 = f2fma(eeB, xa.y, aB1);
            aA2 = f2fma(eeA, xb.x, aA2);  aB2 = f2fma(eeB, xb.x, aB2);
            aA3 = f2fma(eeA, xb.y, aA3);  aB3 = f2fma(eeB, xb.y, aB3);
            aA4 = f2fma(eeA, xc.x, aA4);  aB4 = f2fma(eeB, xc.x, aB4);  // (t8,1.0)->(acc8,l)
        }
    }
    if (act0) {
        ull* pa = g_pa + ((size_t)((b * SPLITS + s) << 12) + r0) * 5;
        pa[0] = aA0; pa[1] = aA1; pa[2] = aA2; pa[3] = aA3; pa[4] = aA4;
    }
    if (act1) {
        ull* pa = g_pa + ((size_t)((b * SPLITS + s) << 12) + r1) * 5;
        pa[0] = aB0; pa[1] = aB1; pa[2] = aB2; pa[3] = aB3; pa[4] = aB4;
    }
    // split-arrival; last block of this (b,x) group reduces (fixed s order => deterministic)
    __syncthreads();
    if (t == 0) {
        __threadfence();
        int old = atomicAdd(&g_cnt[b * GX + x], 1);
        s_win = (old == SPLITS - 1) ? 1 : 0;
        if (s_win) g_cnt[b * GX + x] = 0;        // reset for next graph replay
    }
    __syncthreads();
    if (s_win) {
        ull z2 = pk2(0.f, 0.f);
        #pragma unroll
        for (int rr = 0; rr < 2; rr++) {
            int r = (rr == 0) ? r0 : r1;
            bool act = (rr == 0) ? act0 : act1;
            if (!act) continue;
            int n = g_need[r];
            float M2v = g_M[(b << 12) + n];
            ull c0 = z2, c1 = z2, c2 = z2, c3 = z2;
            ull c4 = pk2(0.f, (float)(PP - nvalid) * ex2f(-M2v));  // masked keys' denominator
            #pragma unroll
            for (int ss2 = 0; ss2 < SPLITS; ss2++) {
                const ull* pa = g_pa + ((size_t)((b * SPLITS + ss2) << 12) + r) * 5;
                c0 = f2add(c0, pa[0]);
                c1 = f2add(c1, pa[1]);
                c2 = f2add(c2, pa[2]);
                c3 = f2add(c3, pa[3]);
                c4 = f2add(c4, pa[4]);
            }
            float f[10];
            upk(c0, f[0], f[1]);
            upk(c1, f[2], f[3]);
            upk(c2, f[4], f[5]);
            upk(c3, f[6], f[7]);
            upk(c4, f[8], f[9]);
            float rl = 1.f / f[9];
            float* dst = g_tmp9 + (size_t)((b << 12) + n) * 9;
            #pragma unroll
            for (int k = 0; k < 9; k++) dst[k] = f[k] * rl;
        }
    }
}

// ---------------- KF: transpose-conv gather + final elementwise (loads hoisted) ----------------
__global__ void kF_final(const float* __restrict__ inp, const float* __restrict__ mask,
                         const float* __restrict__ bias, float* __restrict__ out) {
    int t = threadIdx.x;
    int lane = t & 31;
    int sub = lane & 15;
    int gw = blockIdx.x * 16 + (t >> 5) * 2 + (lane >> 4);   // pixel index b*4096+p
    int p = gw & 4095, b = gw >> 12, y = p >> 6, x = p & 63;
    // hoist independent streaming loads ahead of the dependent gather/reduce chain
    int base4 = gw << 5;
    int pbase4 = p << 5;
    int c4a = sub, c4b = sub + 16;
    float4 iva = ((const float4*)inp)[base4 + c4a];
    float4 ivb = ((const float4*)inp)[base4 + c4b];
    float4 bva = ((const float4*)bias)[pbase4 + c4a];
    float4 bvb = ((const float4*)bias)[pbase4 + c4b];
    float sg = g_sig[gw];
    float mv = mask[p];
    float ysum = 0.f;
    if (mv < 0.5f && sub < 9) {
        int kh = sub / 3, kw = sub % 3;
        int ny = y - (kh - 1), nx = x - (kw - 1);
        if (ny >= 0 && ny < HH && nx >= 0 && nx < WW)
            ysum = g_tmp9[(size_t)((b << 12) + (ny << 6) + nx) * 9 + sub];
    }
    #pragma unroll
    for (int o = 8; o; o >>= 1)
        ysum += __shfl_xor_sync(0xffffffffu, ysum, o);
    float yb = ysum * 0.25f;
    float w = 1.0f - mv;
    float4 o4;
    o4.x = sg * (iva.x + (yb + bva.x) * w);
    o4.y = sg * (iva.y + (yb + bva.y) * w);
    o4.z = sg * (iva.z + (yb + bva.z) * w);
    o4.w = sg * (iva.w + (yb + bva.w) * w);
    ((float4*)out)[base4 + c4a] = o4;
    float4 o5;
    o5.x = sg * (ivb.x + (yb + bvb.x) * w);
    o5.y = sg * (ivb.y + (yb + bvb.y) * w);
    o5.z = sg * (ivb.z + (yb + bvb.z) * w);
    o5.w = sg * (ivb.w + (yb + bvb.w) * w);
    ((float4*)out)[base4 + c4b] = o5;
}

// ---------------- launch ----------------
extern "C" void kernel_launch(void* const* d_in, const int* in_sizes, int n_in,
                              void* d_out, int out_size) {
    const float* inp   = (const float*)d_in[0];
    const float* mask  = (const float*)d_in[1];
    const float* bias  = (const float*)d_in[2];
    const float* convw = (const float*)d_in[3];
    float* out = (float*)d_out;

    kA<<<513, 256>>>(inp, mask);
    kB_patches<<<(BB * PP) / 256, 256>>>(convw);
    dim3 gD(GX, BB, SPLITS);
    kD_attn<<<gD, 128>>>();
    kF_final<<<(BB * PP) / 16, 256>>>(inp, mask, bias, out);
}

// round 17
// speedup vs baseline: 1.1673x; 1.0005x over previous
#include <cuda_runtime.h>
#include <math.h>

#define BB 4
#define HH 64
#define WW 64
#define CC 128
#define PP 4096
#define SPLITS 18
#define GX 16
#define ROWS_PB 256
#define LOG2E 1.44269504088896340736f

typedef unsigned long long ull;

// ---------------- static scratch ----------------
__device__ float g_x[BB * PP * 2];          // per-pixel (mean, max)
__device__ float g_xfq[BB * PP * 20];       // queries pre-scaled by LOG2E, 18+2 pad
__device__ float g_M[BB * PP];              // M2 = patch L2 norm * LOG2E
__device__ float g_wn[BB * PP * 20];        // compacted normalized keys, 18+2 pad
__device__ float g_xfe[BB * PP * 12];       // compacted taps [t0..t8, 1.0, 0, 0]
__device__ float g_sig[BB * PP];            // sigmoid(gate conv)
__device__ int   g_vrank[PP];               // pixel -> compacted key index (or -1)
__device__ int   g_need[PP];
__device__ int   g_counts[2];               // [0]=n_valid, [1]=n_need
__device__ ull   g_pa[(size_t)BB * SPLITS * PP * 5];  // packed split partials (9 taps + l)
__device__ float g_tmp9[BB * PP * 9];
__device__ int   g_cnt[BB * GX];            // split arrival counters (self-resetting)

// ---- packed f32x2 helpers ----
__device__ __forceinline__ ull pk2(float lo, float hi) {
    ull r; asm("mov.b64 %0, {%1, %2};" : "=l"(r) : "f"(lo), "f"(hi)); return r;
}
__device__ __forceinline__ void upk(ull v, float& lo, float& hi) {
    asm("mov.b64 {%0, %1}, %2;" : "=f"(lo), "=f"(hi) : "l"(v));
}
__device__ __forceinline__ ull f2fma(ull a, ull b, ull c) {
    ull d; asm("fma.rn.f32x2 %0, %1, %2, %3;" : "=l"(d) : "l"(a), "l"(b), "l"(c)); return d;
}
__device__ __forceinline__ ull f2mul(ull a, ull b) {
    ull d; asm("mul.rn.f32x2 %0, %1, %2;" : "=l"(d) : "l"(a), "l"(b)); return d;
}
__device__ __forceinline__ ull f2add(ull a, ull b) {
    ull d; asm("add.rn.f32x2 %0, %1, %2;" : "=l"(d) : "l"(a), "l"(b)); return d;
}
__device__ __forceinline__ float ex2f(float x) {
    float r; asm("ex2.approx.f32 %0, %1;" : "=f"(r) : "f"(x)); return r;
}

// ---------------- KA: mean/max (blocks 0..511, 4 pixels/warp, MLP=4) + compaction (block 512) ----------------
__global__ void kA(const float* __restrict__ inp, const float* __restrict__ mask) {
    __shared__ int wv[8], wn_[8];
    if (blockIdx.x == 512) {
        int t = threadIdx.x;
        int lane = t & 31, wid = t >> 5;
        unsigned fv = 0, fn = 0;
        int cv = 0, cn = 0;
        int base_p = t * 16;
        for (int i = 0; i < 16; i++) {
            int p = base_p + i, y = p >> 6, x = p & 63;
            int allone = 1, anyz = 0;
            #pragma unroll
            for (int dy = -1; dy <= 1; dy++)
                #pragma unroll
                for (int dx = -1; dx <= 1; dx++) {
                    int yy = y + dy, xx = x + dx;
                    if (yy < 0 || yy >= HH || xx < 0 || xx >= WW) {
                        allone = 0;
                    } else {
                        float mv = mask[(yy << 6) + xx];
                        if (mv < 0.5f) { allone = 0; anyz = 1; }
                    }
                }
            if (allone) { fv |= (1u << i); cv++; }
            if (anyz)   { fn |= (1u << i); cn++; }
        }
        int iv = cv, inn = cn;
        #pragma unroll
        for (int o = 1; o < 32; o <<= 1) {
            int a = __shfl_up_sync(0xffffffffu, iv, o);
            int b = __shfl_up_sync(0xffffffffu, inn, o);
            if (lane >= o) { iv += a; inn += b; }
        }
        if (lane == 31) { wv[wid] = iv; wn_[wid] = inn; }
        __syncthreads();
        int bv = 0, bn = 0;
        for (int i = 0; i < wid; i++) { bv += wv[i]; bn += wn_[i]; }
        int offv = bv + iv - cv;
        int offn = bn + inn - cn;
        for (int i = 0; i < 16; i++) {
            int p = base_p + i;
            if (fv & (1u << i)) g_vrank[p] = offv++;
            else                g_vrank[p] = -1;
            if (fn & (1u << i)) g_need[offn++] = p;
        }
        if (t == 255) { g_counts[0] = bv + iv; g_counts[1] = bn + inn; }
        return;
    }
    // 4 pixels per warp: 8-lane group each, 4 independent float4 loads per thread
    int lane = threadIdx.x & 31;
    int pix = blockIdx.x * 32 + (threadIdx.x >> 5) * 4 + (lane >> 3);
    int sub = lane & 7;
    const float4* base = (const float4*)(inp + (size_t)pix * CC);
    float4 v0 = base[sub];
    float4 v1 = base[sub + 8];
    float4 v2 = base[sub + 16];
    float4 v3 = base[sub + 24];
    float s = (((v0.x + v0.y) + (v0.z + v0.w)) + ((v1.x + v1.y) + (v1.z + v1.w)))
            + (((v2.x + v2.y) + (v2.z + v2.w)) + ((v3.x + v3.y) + (v3.z + v3.w)));
    float m = fmaxf(
        fmaxf(fmaxf(fmaxf(v0.x, v0.y), fmaxf(v0.z, v0.w)),
              fmaxf(fmaxf(v1.x, v1.y), fmaxf(v1.z, v1.w))),
        fmaxf(fmaxf(fmaxf(v2.x, v2.y), fmaxf(v2.z, v2.w)),
              fmaxf(fmaxf(v3.x, v3.y), fmaxf(v3.z, v3.w))));
    #pragma unroll
    for (int o = 4; o; o >>= 1) {
        s += __shfl_xor_sync(0xffffffffu, s, o);
        m = fmaxf(m, __shfl_xor_sync(0xffffffffu, m, o));
    }
    if (sub == 0) {
        g_x[pix * 2 + 0] = s * (1.0f / 128.0f);
        g_x[pix * 2 + 1] = m;
    }
}

// ---------------- KB: smem-tiled patches + norms + keys/values + gate conv ----------------
// 16x16 pixel tile per block; (16+6)^2 float2 halo staged in smem (zero-fill = SAME padding).
__global__ void kB_patches(const float* __restrict__ convw) {
    __shared__ float2 sx2[22 * 22];
    __shared__ float swq[98];
    int t = threadIdx.x;
    int b = blockIdx.y;
    int tileY = blockIdx.x >> 2, tileX = blockIdx.x & 3;
    int ty0 = tileY * 16 - 3, tx0 = tileX * 16 - 3;
    const float2* gx2 = (const float2*)g_x;
    #pragma unroll
    for (int i = t; i < 484; i += 256) {
        int sy = i / 22, sx = i % 22;
        int gy = ty0 + sy, gx = tx0 + sx;
        float2 val = make_float2(0.f, 0.f);
        if (gy >= 0 && gy < HH && gx >= 0 && gx < WW)
            val = gx2[(b << 12) + (gy << 6) + gx];
        sx2[i] = val;
    }
    if (t < 98) swq[t] = convw[t];
    __syncthreads();

    int py = tileY * 16 + (t >> 4), px = tileX * 16 + (t & 15);
    int ly = (t >> 4) + 3, lx = (t & 15) + 3;
    int p = (py << 6) + px;
    int idx = (b << 12) + p;

    float v[18];
    float ss = 0.f;
    int j = 0;
    #pragma unroll
    for (int kh = 0; kh < 3; kh++)
        #pragma unroll
        for (int kw = 0; kw < 3; kw++) {
            float2 gv = sx2[(ly + kh - 1) * 22 + (lx + kw - 1)];
            v[j] = gv.x; v[j + 1] = gv.y;
            ss += gv.x * gv.x + gv.y * gv.y;
            j += 2;
        }
    float Mn = sqrtf(ss);
    // query: pre-scaled by LOG2E
    float* dst = g_xfq + (size_t)idx * 20;
    #pragma unroll
    for (int i = 0; i < 18; i++) dst[i] = v[i] * LOG2E;
    dst[18] = 0.f; dst[19] = 0.f;
    g_M[idx] = Mn * LOG2E;
    // key/value if this pixel is a fully-valid patch
    int vr = g_vrank[p];
    if (vr >= 0) {
        float rn = 1.f / fmaxf(Mn, 1e-4f);
        float* dw = g_wn + (size_t)((b << 12) + vr) * 20;
        #pragma unroll
        for (int i = 0; i < 18; i++) dw[i] = v[i] * rn;
        dw[18] = 0.f; dw[19] = 0.f;
        float* de = g_xfe + (size_t)((b << 12) + vr) * 12;
        #pragma unroll
        for (int k = 0; k < 9; k++) de[k] = v[2 * k];
        de[9] = 1.0f;          // synthetic tap: accumulates the softmax denominator
        de[10] = 0.f; de[11] = 0.f;
    }
    // 7x7x2 gate conv + sigmoid, all from smem (halo zeros = SAME padding)
    float g = 0.f;
    #pragma unroll
    for (int u = 0; u < 7; u++)
        #pragma unroll
        for (int vv = 0; vv < 7; vv++) {
            float2 gv = sx2[(ly + u - 3) * 22 + (lx + vv - 3)];
            g += gv.x * swq[(u * 7 + vv) * 2 + 0]
               + gv.y * swq[(u * 7 + vv) * 2 + 1];
        }
    g_sig[idx] = 1.f / (1.f + __expf(-g));
}

// ---------------- KD: fused attention (f32x2, 2 rows/thread), deep split-K single wave ----------------
__global__ void __launch_bounds__(128, 5) kD_attn() {
    __shared__ ulonglong2 swn[128 * 5];  // key dim-pairs
    __shared__ ulonglong2 sxe[128 * 3];  // tap pairs (t0,t1)..(t8,1.0)
    __shared__ int s_win;
    int nneed = g_counts[1];
    int x = blockIdx.x, b = blockIdx.y, s = blockIdx.z;
    if (x * ROWS_PB >= nneed) return;
    int nvalid = g_counts[0];
    int chunk = (nvalid + SPLITS - 1) / SPLITS;
    int v0 = s * chunk;
    int v1 = min(v0 + chunk, nvalid);
    int t = threadIdx.x;
    int r0 = x * ROWS_PB + t;
    int r1 = r0 + 128;
    bool act0 = r0 < nneed, act1 = r1 < nneed;

    ull qA[9], qB[9];
    ull initA, initB;
    {
        int n = g_need[r0];
        const ulonglong2* qp = (const ulonglong2*)(g_xfq + (size_t)((b << 12) + n) * 20);
        ulonglong2 a_ = qp[0], b_ = qp[1], c_ = qp[2], d_ = qp[3], e_ = qp[4];
        qA[0] = a_.x; qA[1] = a_.y; qA[2] = b_.x; qA[3] = b_.y; qA[4] = c_.x;
        qA[5] = c_.y; qA[6] = d_.x; qA[7] = d_.y; qA[8] = e_.x;
        initA = pk2(-g_M[(b << 12) + n], 0.f);   // fold -M2 into the dot
    }
    {
        int n = g_need[r1];
        const ulonglong2* qp = (const ulonglong2*)(g_xfq + (size_t)((b << 12) + n) * 20);
        ulonglong2 a_ = qp[0], b_ = qp[1], c_ = qp[2], d_ = qp[3], e_ = qp[4];
        qB[0] = a_.x; qB[1] = a_.y; qB[2] = b_.x; qB[3] = b_.y; qB[4] = c_.x;
        qB[5] = c_.y; qB[6] = d_.x; qB[7] = d_.y; qB[8] = e_.x;
        initB = pk2(-g_M[(b << 12) + n], 0.f);
    }
    ull z = pk2(0.f, 0.f);
    ull aA0 = z, aA1 = z, aA2 = z, aA3 = z, aA4 = z;
    ull aB0 = z, aB1 = z, aB2 = z, aB3 = z, aB4 = z;

    for (int base = v0; base < v1; base += 128) {
        int cnt = min(128, v1 - base);
        __syncthreads();
        if (t < cnt) {
            const ulonglong2* srcw = (const ulonglong2*)(g_wn + (size_t)((b << 12) + base + t) * 20);
            #pragma unroll
            for (int w = 0; w < 5; w++) swn[t * 5 + w] = srcw[w];
            const ulonglong2* srcx = (const ulonglong2*)(g_xfe + (size_t)((b << 12) + base + t) * 12);
            #pragma unroll
            for (int w = 0; w < 3; w++) sxe[t * 3 + w] = srcx[w];
        }
        __syncthreads();
        for (int j = 0; j < cnt; j++) {
            ulonglong2 wa = swn[j * 5], wb = swn[j * 5 + 1], wc = swn[j * 5 + 2], wd = swn[j * 5 + 3];
            ull w8 = swn[j * 5 + 4].x;
            // row A: two independent chains, -M2 pre-folded
            ull m0 = f2fma(qA[0], wa.x, initA);
            ull m1 = f2mul(qA[1], wa.y);
            m0 = f2fma(qA[2], wb.x, m0);
            m1 = f2fma(qA[3], wb.y, m1);
            m0 = f2fma(qA[4], wc.x, m0);
            m1 = f2fma(qA[5], wc.y, m1);
            m0 = f2fma(qA[6], wd.x, m0);
            m1 = f2fma(qA[7], wd.y, m1);
            m0 = f2fma(qA[8], w8, m0);
            // row B
            ull n0 = f2fma(qB[0], wa.x, initB);
            ull n1 = f2mul(qB[1], wa.y);
            n0 = f2fma(qB[2], wb.x, n0);
            n1 = f2fma(qB[3], wb.y, n1);
            n0 = f2fma(qB[4], wc.x, n0);
            n1 = f2fma(qB[5], wc.y, n1);
            n0 = f2fma(qB[6], wd.x, n0);
            n1 = f2fma(qB[7], wd.y, n1);
            n0 = f2fma(qB[8], w8, n0);
            ull sa = f2add(m0, m1);
            ull sb = f2add(n0, n1);
            float alo, ahi, blo, bhi;
            upk(sa, alo, ahi);
            upk(sb, blo, bhi);
            float eA = ex2f(alo + ahi);          // score - M2 <= 0 always (||wn||<=1)
            float eB = ex2f(blo + bhi);
            ull eeA = pk2(eA, eA);
            ull eeB = pk2(eB, eB);
            ulonglong2 xa = sxe[j * 3], xb = sxe[j * 3 + 1], xc = sxe[j * 3 + 2];
            aA0 = f2fma(eeA, xa.x, aA0);  aB0 = f2fma(eeB, xa.x, aB0);
            aA1 = f2fma(eeA, xa.y, aA1);  aB1 = f2fma(eeB, xa.y, aB1);
            aA2 = f2fma(eeA, xb.x, aA2);  aB2 = f2fma(eeB, xb.x, aB2);
            aA3 = f2fma(eeA, xb.y, aA3);  aB3 = f2fma(eeB, xb.y, aB3);
            aA4 = f2fma(eeA, xc.x, aA4);  aB4 = f2fma(eeB, xc.x, aB4);  // (t8,1.0)->(acc8,l)
        }
    }
    if (act0) {
        ull* pa = g_pa + ((size_t)((b * SPLITS + s) << 12) + r0) * 5;
        pa[0] = aA0; pa[1] = aA1; pa[2] = aA2; pa[3] = aA3; pa[4] = aA4;
    }
    if (act1) {
        ull* pa = g_pa + ((size_t)((b * SPLITS + s) << 12) + r1) * 5;
        pa[0] = aB0; pa[1] = aB1; pa[2] = aB2; pa[3] = aB3; pa[4] = aB4;
    }
    // split-arrival; last block of this (b,x) group reduces (fixed s order => deterministic)
    __syncthreads();
    if (t == 0) {
        __threadfence();
        int old = atomicAdd(&g_cnt[b * GX + x], 1);
        s_win = (old == SPLITS - 1) ? 1 : 0;
        if (s_win) g_cnt[b * GX + x] = 0;        // reset for next graph replay
    }
    __syncthreads();
    if (s_win) {
        ull z2 = pk2(0.f, 0.f);
        #pragma unroll
        for (int rr = 0; rr < 2; rr++) {
            int r = (rr == 0) ? r0 : r1;
            bool act = (rr == 0) ? act0 : act1;
            if (!act) continue;
            int n = g_need[r];
            float M2v = g_M[(b << 12) + n];
            ull c0 = z2, c1 = z2, c2 = z2, c3 = z2;
            ull c4 = pk2(0.f, (float)(PP - nvalid) * ex2f(-M2v));  // masked keys' denominator
            #pragma unroll
            for (int ss2 = 0; ss2 < SPLITS; ss2++) {
                const ull* pa = g_pa + ((size_t)((b * SPLITS + ss2) << 12) + r) * 5;
                c0 = f2add(c0, pa[0]);
                c1 = f2add(c1, pa[1]);
                c2 = f2add(c2, pa[2]);
                c3 = f2add(c3, pa[3]);
                c4 = f2add(c4, pa[4]);
            }
            float f[10];
            upk(c0, f[0], f[1]);
            upk(c1, f[2], f[3]);
            upk(c2, f[4], f[5]);
            upk(c3, f[6], f[7]);
            upk(c4, f[8], f[9]);
            float rl = 1.f / f[9];
            float* dst = g_tmp9 + (size_t)((b << 12) + n) * 9;
            #pragma unroll
            for (int k = 0; k < 9; k++) dst[k] = f[k] * rl;
        }
    }
}

// ---------------- KF: transpose-conv gather + final elementwise (loads hoisted) ----------------
__global__ void kF_final(const float* __restrict__ inp, const float* __restrict__ mask,
                         const float* __restrict__ bias, float* __restrict__ out) {
    int t = threadIdx.x;
    int lane = t & 31;
    int sub = lane & 15;
    int gw = blockIdx.x * 16 + (t >> 5) * 2 + (lane >> 4);   // pixel index b*4096+p
    int p = gw & 4095, b = gw >> 12, y = p >> 6, x = p & 63;
    // hoist independent streaming loads ahead of the dependent gather/reduce chain
    int base4 = gw << 5;
    int pbase4 = p << 5;
    int c4a = sub, c4b = sub + 16;
    float4 iva = ((const float4*)inp)[base4 + c4a];
    float4 ivb = ((const float4*)inp)[base4 + c4b];
    float4 bva = ((const float4*)bias)[pbase4 + c4a];
    float4 bvb = ((const float4*)bias)[pbase4 + c4b];
    float sg = g_sig[gw];
    float mv = mask[p];
    float ysum = 0.f;
    if (mv < 0.5f && sub < 9) {
        int kh = sub / 3, kw = sub % 3;
        int ny = y - (kh - 1), nx = x - (kw - 1);
        if (ny >= 0 && ny < HH && nx >= 0 && nx < WW)
            ysum = g_tmp9[(size_t)((b << 12) + (ny << 6) + nx) * 9 + sub];
    }
    #pragma unroll
    for (int o = 8; o; o >>= 1)
        ysum += __shfl_xor_sync(0xffffffffu, ysum, o);
    float yb = ysum * 0.25f;
    float w = 1.0f - mv;
    float4 o4;
    o4.x = sg * (iva.x + (yb + bva.x) * w);
    o4.y = sg * (iva.y + (yb + bva.y) * w);
    o4.z = sg * (iva.z + (yb + bva.z) * w);
    o4.w = sg * (iva.w + (yb + bva.w) * w);
    ((float4*)out)[base4 + c4a] = o4;
    float4 o5;
    o5.x = sg * (ivb.x + (yb + bvb.x) * w);
    o5.y = sg * (ivb.y + (yb + bvb.y) * w);
    o5.z = sg * (ivb.z + (yb + bvb.z) * w);
    o5.w = sg * (ivb.w + (yb + bvb.w) * w);
    ((float4*)out)[base4 + c4b] = o5;
}

// ---------------- launch ----------------
extern "C" void kernel_launch(void* const* d_in, const int* in_sizes, int n_in,
                              void* d_out, int out_size) {
    const float* inp   = (const float*)d_in[0];
    const float* mask  = (const float*)d_in[1];
    const float* bias  = (const float*)d_in[2];
    const float* convw = (const float*)d_in[3];
    float* out = (float*)d_out;

    kA<<<513, 256>>>(inp, mask);
    dim3 gB(16, BB);
    kB_patches<<<gB, 256>>>(convw);
    dim3 gD(GX, BB, SPLITS);
    kD_attn<<<gD, 128>>>();
    kF_final<<<(BB * PP) / 16, 256>>>(inp, mask, bias, out);
}